// round 7
// baseline (speedup 1.0000x reference)
#include <cuda_runtime.h>
#include <cstdint>

// Problem constants (fixed by the reference)
#define NU 200000
#define NI 400000
#define NN 600000          // NU + NI
#define DD 32
#define NH 128
#define NE 10000000

#define GB_USER 384
#define GB_ITEM 768
#define NB_SCAN 147        // ceil(NN / 4096)

// Scratch: device globals (no allocation allowed)
__device__ __align__(256) float g_bufA[(size_t)NN * DD];
__device__ __align__(256) float g_bufB[(size_t)NN * DD];
__device__ __align__(256) float g_G[2][DD * DD];
__device__ __align__(256) float g_M[2][DD * DD];
__device__ __align__(16)  int2  g_csr[NE];       // (col, bitcast(val)) in CSR order
__device__ int g_cnt[NN];
__device__ int g_start[NN];
__device__ int g_cur[NN];
__device__ int g_blkSum[256];
__device__ int g_blkOff[256];
__device__ int g_is64;

// ---------------- helpers ----------------
__device__ __forceinline__ float4 f4_fma(float a, float4 b, float4 c) {
    c.x = fmaf(a, b.x, c.x);
    c.y = fmaf(a, b.y, c.y);
    c.z = fmaf(a, b.z, c.z);
    c.w = fmaf(a, b.w, c.w);
    return c;
}

__device__ __forceinline__ float lrelu(float x) {
    return fmaxf(x, 0.5f * x);   // negative_slope = 0.5
}

// ---------------- setup kernels ----------------

// Detect whether adj_idx is int64 (x64 refs) or int32.
__global__ void k_detect(const int* __restrict__ adj) {
    if (threadIdx.x == 0 && blockIdx.x == 0) {
        int odd_or = 0;
        #pragma unroll 8
        for (int i = 1; i < 2048; i += 2) odd_or |= adj[i];
        g_is64 = (odd_or == 0) ? 1 : 0;
    }
}

// prev(A) = concat(user_emb, item_emb); out = same (accumulator seed)
__global__ void __launch_bounds__(256)
k_init(const float* __restrict__ ue, const float* __restrict__ ie,
       float* __restrict__ out) {
    size_t i = (size_t)blockIdx.x * blockDim.x + threadIdx.x;   // float4 index
    const size_t nu4 = (size_t)NU * DD / 4;
    const size_t tot = (size_t)NN * DD / 4;
    if (i >= tot) return;
    float4 v = (i < nu4) ? ((const float4*)ue)[i] : ((const float4*)ie)[i - nu4];
    ((float4*)g_bufA)[i] = v;
    ((float4*)out)[i] = v;
}

__global__ void __launch_bounds__(256)
k_zero_cnt() {
    int i = blockIdx.x * 256 + threadIdx.x;
    if (i < NN) g_cnt[i] = 0;
}

// ---------------- CSR build ----------------

__global__ void __launch_bounds__(256)
k_hist(const int* __restrict__ adj) {
    size_t e = (size_t)blockIdx.x * 256 + threadIdx.x;
    if (e >= (size_t)NE) return;
    int r = g_is64 ? (int)((const long long*)adj)[e] : adj[e];
    atomicAdd(&g_cnt[r], 1);
}

// scan1: per-block (4096 counts) sums
__global__ void __launch_bounds__(1024)
k_scan1() {
    int blk = blockIdx.x, t = threadIdx.x;
    int idx = blk * 4096 + t * 4;
    int s = 0;
    #pragma unroll
    for (int j = 0; j < 4; j++) { int ii = idx + j; if (ii < NN) s += g_cnt[ii]; }
    #pragma unroll
    for (int o = 16; o; o >>= 1) s += __shfl_down_sync(0xffffffffu, s, o);
    __shared__ int wsh[32];
    if ((t & 31) == 0) wsh[t >> 5] = s;
    __syncthreads();
    if (t < 32) {
        int x = wsh[t];
        #pragma unroll
        for (int o = 16; o; o >>= 1) x += __shfl_down_sync(0xffffffffu, x, o);
        if (t == 0) g_blkSum[blk] = x;
    }
}

// scan2: exclusive scan of the block sums (single block, 256 threads)
__global__ void __launch_bounds__(256)
k_scan2() {
    __shared__ int sh[256];
    int t = threadIdx.x;
    int v = (t < NB_SCAN) ? g_blkSum[t] : 0;
    sh[t] = v;
    __syncthreads();
    #pragma unroll
    for (int o = 1; o < 256; o <<= 1) {
        int u = 0;
        if (t >= o) u = sh[t - o];
        __syncthreads();
        if (t >= o) sh[t] += u;
        __syncthreads();
    }
    if (t < NB_SCAN) g_blkOff[t] = sh[t] - v;   // exclusive
}

// scan3: full exclusive scan -> g_start, g_cur
__global__ void __launch_bounds__(1024)
k_scan3() {
    __shared__ int wsum[32];
    int blk = blockIdx.x, t = threadIdx.x;
    int lane = t & 31, w = t >> 5;
    int idx = blk * 4096 + t * 4;
    int c0 = 0, c1 = 0, c2 = 0, c3 = 0;
    if (idx     < NN) c0 = g_cnt[idx];
    if (idx + 1 < NN) c1 = g_cnt[idx + 1];
    if (idx + 2 < NN) c2 = g_cnt[idx + 2];
    if (idx + 3 < NN) c3 = g_cnt[idx + 3];
    int ts = c0 + c1 + c2 + c3;
    int v = ts;
    #pragma unroll
    for (int o = 1; o < 32; o <<= 1) {
        int u = __shfl_up_sync(0xffffffffu, v, o);
        if (lane >= o) v += u;
    }
    if (lane == 31) wsum[w] = v;
    __syncthreads();
    if (w == 0) {
        int x = wsum[lane];
        #pragma unroll
        for (int o = 1; o < 32; o <<= 1) {
            int u = __shfl_up_sync(0xffffffffu, x, o);
            if (lane >= o) x += u;
        }
        wsum[lane] = x;
    }
    __syncthreads();
    int excl = v - ts + (w ? wsum[w - 1] : 0) + g_blkOff[blk];
    if (idx     < NN) { g_start[idx]     = excl;           g_cur[idx]     = excl; }
    if (idx + 1 < NN) { g_start[idx + 1] = excl + c0;      g_cur[idx + 1] = excl + c0; }
    if (idx + 2 < NN) { g_start[idx + 2] = excl + c0 + c1; g_cur[idx + 2] = excl + c0 + c1; }
    if (idx + 3 < NN) { g_start[idx + 3] = excl + c0 + c1 + c2; g_cur[idx + 3] = excl + c0 + c1 + c2; }
}

__global__ void __launch_bounds__(256)
k_scatter(const int* __restrict__ adj, const float* __restrict__ vals) {
    size_t e = (size_t)blockIdx.x * 256 + threadIdx.x;
    if (e >= (size_t)NE) return;
    int r, c;
    if (g_is64) {
        const long long* a64 = (const long long*)adj;
        r = (int)a64[e];
        c = (int)a64[(size_t)NE + e];
    } else {
        r = adj[e];
        c = adj[(size_t)NE + e];
    }
    float v = __ldcs(vals + e);
    int pos = atomicAdd(&g_cur[r], 1);
    g_csr[pos] = make_int2(c, __float_as_int(v));
}

// ---------------- per-layer kernels ----------------

__global__ void __launch_bounds__(512)
k_zeroG() {
    int t = threadIdx.x;
    float* g = &g_G[0][0];
    for (int i = t; i < 2 * DD * DD; i += blockDim.x) g[i] = 0.0f;
}

// G[part] = E0_part^T @ prev_part   (32x32 each)
__global__ void __launch_bounds__(256, 2)
k_G(const float* __restrict__ ue, const float* __restrict__ ie, int dir) {
    const float* prev = dir ? g_bufB : g_bufA;
    int b = blockIdx.x;
    const float* e0; const float* pv; float* Gout; int r0, r1;
    if (b < GB_USER) {
        e0 = ue; pv = prev; Gout = g_G[0];
        const int per = (NU + GB_USER - 1) / GB_USER;
        r0 = b * per; r1 = min(r0 + per, NU);
    } else {
        int bb = b - GB_USER;
        e0 = ie; pv = prev + (size_t)NU * DD; Gout = g_G[1];
        const int per = (NI + GB_ITEM - 1) / GB_ITEM;
        r0 = bb * per; r1 = min(r0 + per, NI);
    }
    int t = threadIdx.x;
    int q  = t >> 6;          // row subgroup 0..3
    int g  = t & 63;          // cell-thread 0..63
    int a4 = g >> 3;          // rows a4*4..+3 of G
    int b4 = g & 7;           // cols b4*4..+3 of G

    float4 acc0 = {0,0,0,0}, acc1 = {0,0,0,0}, acc2 = {0,0,0,0}, acc3 = {0,0,0,0};

    #pragma unroll 2
    for (int r = r0 + q; r < r1; r += 4) {
        float4 e4 = *(const float4*)(e0 + (size_t)r * DD + a4 * 4);
        float4 p4 = *(const float4*)(pv + (size_t)r * DD + b4 * 4);
        acc0 = f4_fma(e4.x, p4, acc0);
        acc1 = f4_fma(e4.y, p4, acc1);
        acc2 = f4_fma(e4.z, p4, acc2);
        acc3 = f4_fma(e4.w, p4, acc3);
    }

    __shared__ float red[4 * 1024];
    float* my = red + q * 1024 + g * 16;
    ((float4*)my)[0] = acc0;
    ((float4*)my)[1] = acc1;
    ((float4*)my)[2] = acc2;
    ((float4*)my)[3] = acc3;
    __syncthreads();

    for (int idx = t; idx < 1024; idx += 256) {
        int gg = idx >> 4, i = idx & 15;
        float s = red[0 * 1024 + gg * 16 + i] + red[1 * 1024 + gg * 16 + i]
                + red[2 * 1024 + gg * 16 + i] + red[3 * 1024 + gg * 16 + i];
        int a  = (gg >> 3) * 4 + (i >> 2);
        int bc = (gg & 7) * 4 + (i & 3);
        atomicAdd(&Gout[a * DD + bc], s);
    }
}

// M[part] = W (W^T G[part]);  W is [32,128] row-major. grid = 2 blocks, 256 thr.
__global__ void __launch_bounds__(256, 1)
k_M(const float* __restrict__ uW, const float* __restrict__ iW) {
    int part = blockIdx.x;
    const float* W = part ? iW : uW;
    __shared__ float Wsh[32 * NH];
    __shared__ float Tsh[NH * 32];
    __shared__ float Gsh[32 * 32];
    int t = threadIdx.x;
    for (int i = t; i < 32 * NH; i += 256) Wsh[i] = W[i];
    for (int i = t; i < 1024; i += 256) Gsh[i] = g_G[part][i];
    __syncthreads();
    for (int idx = t; idx < NH * 32; idx += 256) {
        int h = idx >> 5, bcol = idx & 31;
        float s = 0.0f;
        #pragma unroll 8
        for (int a = 0; a < 32; a++) s = fmaf(Wsh[a * NH + h], Gsh[a * 32 + bcol], s);
        Tsh[h * 32 + bcol] = s;
    }
    __syncthreads();
    for (int idx = t; idx < 1024; idx += 256) {
        int a = idx >> 5, bcol = idx & 31;
        float s = 0.0f;
        #pragma unroll 8
        for (int h = 0; h < NH; h++) s = fmaf(Wsh[a * NH + h], Tsh[h * 32 + bcol], s);
        g_M[part][idx] = s;
    }
}

// Fused per-layer: next[r] = gcn(prev)[r] + lrelu(E0[r] @ M[part]); out[r] += next[r].
// One warp per row; lane = output column. CSR gather, no atomics.
__global__ void __launch_bounds__(256)
k_fused(const float* __restrict__ ue, const float* __restrict__ ie,
        float* __restrict__ out, int dir) {
    const float* src = dir ? g_bufB : g_bufA;
    float*       nxt = dir ? g_bufA : g_bufB;

    __shared__ float Msh[2 * 1024];
    int t = threadIdx.x;
    #pragma unroll
    for (int i = 0; i < 8; i++) Msh[i * 256 + t] = ((const float*)g_M)[i * 256 + t];
    __syncthreads();

    int w = t >> 5, lane = t & 31;
    int r = blockIdx.x * 8 + w;
    if (r >= NN) return;

    const float* e0;
    const float* Mp;
    if (r < NU) { e0 = ue + (size_t)r * DD;        Mp = Msh; }
    else        { e0 = ie + (size_t)(r - NU) * DD; Mp = Msh + 1024; }

    // hyp: lrelu(E0[r] @ M)
    float e = e0[lane];
    float acc_h = 0.0f;
    #pragma unroll
    for (int k = 0; k < 32; k++) {
        float ek = __shfl_sync(0xffffffffu, e, k);
        acc_h = fmaf(ek, Mp[k * 32 + lane], acc_h);
    }
    float acc = lrelu(acc_h);

    // gcn: sum over CSR edges of this row (4-way unroll for MLP)
    int start = g_start[r];
    int end   = start + g_cnt[r];
    int i = start;
    for (; i + 4 <= end; i += 4) {
        int2 cv0 = g_csr[i];
        int2 cv1 = g_csr[i + 1];
        int2 cv2 = g_csr[i + 2];
        int2 cv3 = g_csr[i + 3];
        float s0 = src[(size_t)cv0.x * DD + lane];
        float s1 = src[(size_t)cv1.x * DD + lane];
        float s2 = src[(size_t)cv2.x * DD + lane];
        float s3 = src[(size_t)cv3.x * DD + lane];
        acc = fmaf(__int_as_float(cv0.y), s0, acc);
        acc = fmaf(__int_as_float(cv1.y), s1, acc);
        acc = fmaf(__int_as_float(cv2.y), s2, acc);
        acc = fmaf(__int_as_float(cv3.y), s3, acc);
    }
    for (; i < end; i++) {
        int2 cv = g_csr[i];
        acc = fmaf(__int_as_float(cv.y), src[(size_t)cv.x * DD + lane], acc);
    }

    size_t o = (size_t)r * DD + lane;
    nxt[o] = acc;
    out[o] += acc;
}

// ---------------- launch ----------------
extern "C" void kernel_launch(void* const* d_in, const int* in_sizes, int n_in,
                              void* d_out, int out_size) {
    // Identify inputs by element count (robust to harness ordering)
    const int* adj = nullptr; const float* vals = nullptr;
    const float* ue = nullptr; const float* ie = nullptr;
    const float* h1 = nullptr; const float* h2 = nullptr;
    int i_ue = -1, i_ie = -1;
    for (int i = 0; i < n_in; i++) {
        long long s = in_sizes[i];
        if (s == 2LL * NE)              adj = (const int*)d_in[i];
        else if (s == (long long)NE)    vals = (const float*)d_in[i];
        else if (s == (long long)NU * DD) { ue = (const float*)d_in[i]; i_ue = i; }
        else if (s == (long long)NI * DD) { ie = (const float*)d_in[i]; i_ie = i; }
        else if (s == (long long)DD * NH) { if (!h1) h1 = (const float*)d_in[i]; else h2 = (const float*)d_in[i]; }
    }
    const float* uW; const float* iW;
    if (i_ue < i_ie) { uW = h1; iW = h2; }
    else             { uW = h2; iW = h1; }
    float* out = (float*)d_out;

    const int nb_nd    = (NN * DD / 4 + 255) / 256;           // 18750
    const int nb_edge  = (int)(((size_t)NE + 255) / 256);     // 39063
    const int nb_fused = (NN / 8);                            // 75000
    const int nb_cnt   = (NN + 255) / 256;

    k_detect<<<1, 32>>>(adj);
    k_init<<<nb_nd, 256>>>(ue, ie, out);

    // CSR build (amortized over both layers)
    k_zero_cnt<<<nb_cnt, 256>>>();
    k_hist<<<nb_edge, 256>>>(adj);
    k_scan1<<<NB_SCAN, 1024>>>();
    k_scan2<<<1, 256>>>();
    k_scan3<<<NB_SCAN, 1024>>>();
    k_scatter<<<nb_edge, 256>>>(adj, vals);

    for (int layer = 0; layer < 2; layer++) {
        k_zeroG<<<1, 512>>>();
        k_G<<<GB_USER + GB_ITEM, 256>>>(ue, ie, layer);
        k_M<<<2, 256>>>(uW, iW);
        k_fused<<<nb_fused, 256>>>(ue, ie, out, layer);
    }
}

// round 10
// speedup vs baseline: 1.5442x; 1.5442x over previous
#include <cuda_runtime.h>
#include <cstdint>

// Problem constants (fixed by the reference)
#define NU 200000
#define NI 400000
#define NN 600000          // NU + NI
#define DD 32
#define NH 128
#define NE 10000000

#define GB_USER 384
#define GB_ITEM 768
#define NB_SCAN 147        // ceil(NN / 4096)

// Scratch: device globals (no allocation allowed)
__device__ __align__(256) float g_bufA[(size_t)NN * DD];
__device__ __align__(256) float g_bufB[(size_t)NN * DD];
__device__ __align__(256) float g_G[2][DD * DD];
__device__ __align__(256) float g_M[2][DD * DD];
__device__ __align__(16)  int2  g_csr[NE];       // (col, bitcast(val)) in CSR order
__device__ int g_cnt[NN];
__device__ int g_start[NN];
__device__ int g_cur[NN];
__device__ int g_blkSum[256];
__device__ int g_blkOff[256];
__device__ int g_is64;

// ---------------- helpers ----------------
__device__ __forceinline__ float4 f4_fma(float a, float4 b, float4 c) {
    c.x = fmaf(a, b.x, c.x);
    c.y = fmaf(a, b.y, c.y);
    c.z = fmaf(a, b.z, c.z);
    c.w = fmaf(a, b.w, c.w);
    return c;
}

__device__ __forceinline__ float lrelu(float x) {
    return fmaxf(x, 0.5f * x);   // negative_slope = 0.5
}

// ---------------- setup ----------------

// Fused: zero g_cnt across grid; block 0 thread 0 also does dtype detect.
__global__ void __launch_bounds__(256)
k_dz(const int* __restrict__ adj) {
    int i = blockIdx.x * 256 + threadIdx.x;
    if (i < NN) g_cnt[i] = 0;
    if (i == 0) {
        int odd_or = 0;
        #pragma unroll 8
        for (int j = 1; j < 2048; j += 2) odd_or |= adj[j];
        g_is64 = (odd_or == 0) ? 1 : 0;
    }
}

// prev(A) = concat(user_emb, item_emb); out = same (accumulator seed)
__global__ void __launch_bounds__(256)
k_init(const float* __restrict__ ue, const float* __restrict__ ie,
       float* __restrict__ out) {
    size_t i = (size_t)blockIdx.x * blockDim.x + threadIdx.x;   // float4 index
    const size_t nu4 = (size_t)NU * DD / 4;
    const size_t tot = (size_t)NN * DD / 4;
    if (i >= tot) return;
    float4 v = (i < nu4) ? ((const float4*)ue)[i] : ((const float4*)ie)[i - nu4];
    ((float4*)g_bufA)[i] = v;
    ((float4*)out)[i] = v;
}

// ---------------- CSR build ----------------

__global__ void __launch_bounds__(256)
k_hist(const int* __restrict__ adj) {
    size_t e = (size_t)blockIdx.x * 256 + threadIdx.x;
    if (e >= (size_t)NE) return;
    int r = g_is64 ? (int)__ldcs((const long long*)adj + e) : __ldcs(adj + e);
    atomicAdd(&g_cnt[r], 1);
}

__global__ void __launch_bounds__(1024)
k_scan1() {
    int blk = blockIdx.x, t = threadIdx.x;
    int idx = blk * 4096 + t * 4;
    int s = 0;
    #pragma unroll
    for (int j = 0; j < 4; j++) { int ii = idx + j; if (ii < NN) s += g_cnt[ii]; }
    #pragma unroll
    for (int o = 16; o; o >>= 1) s += __shfl_down_sync(0xffffffffu, s, o);
    __shared__ int wsh[32];
    if ((t & 31) == 0) wsh[t >> 5] = s;
    __syncthreads();
    if (t < 32) {
        int x = wsh[t];
        #pragma unroll
        for (int o = 16; o; o >>= 1) x += __shfl_down_sync(0xffffffffu, x, o);
        if (t == 0) g_blkSum[blk] = x;
    }
}

__global__ void __launch_bounds__(256)
k_scan2() {
    __shared__ int sh[256];
    int t = threadIdx.x;
    int v = (t < NB_SCAN) ? g_blkSum[t] : 0;
    sh[t] = v;
    __syncthreads();
    #pragma unroll
    for (int o = 1; o < 256; o <<= 1) {
        int u = 0;
        if (t >= o) u = sh[t - o];
        __syncthreads();
        if (t >= o) sh[t] += u;
        __syncthreads();
    }
    if (t < NB_SCAN) g_blkOff[t] = sh[t] - v;   // exclusive
}

__global__ void __launch_bounds__(1024)
k_scan3() {
    __shared__ int wsum[32];
    int blk = blockIdx.x, t = threadIdx.x;
    int lane = t & 31, w = t >> 5;
    int idx = blk * 4096 + t * 4;
    int c0 = 0, c1 = 0, c2 = 0, c3 = 0;
    if (idx     < NN) c0 = g_cnt[idx];
    if (idx + 1 < NN) c1 = g_cnt[idx + 1];
    if (idx + 2 < NN) c2 = g_cnt[idx + 2];
    if (idx + 3 < NN) c3 = g_cnt[idx + 3];
    int ts = c0 + c1 + c2 + c3;
    int v = ts;
    #pragma unroll
    for (int o = 1; o < 32; o <<= 1) {
        int u = __shfl_up_sync(0xffffffffu, v, o);
        if (lane >= o) v += u;
    }
    if (lane == 31) wsum[w] = v;
    __syncthreads();
    if (w == 0) {
        int x = wsum[lane];
        #pragma unroll
        for (int o = 1; o < 32; o <<= 1) {
            int u = __shfl_up_sync(0xffffffffu, x, o);
            if (lane >= o) x += u;
        }
        wsum[lane] = x;
    }
    __syncthreads();
    int excl = v - ts + (w ? wsum[w - 1] : 0) + g_blkOff[blk];
    if (idx     < NN) { g_start[idx]     = excl;           g_cur[idx]     = excl; }
    if (idx + 1 < NN) { g_start[idx + 1] = excl + c0;      g_cur[idx + 1] = excl + c0; }
    if (idx + 2 < NN) { g_start[idx + 2] = excl + c0 + c1; g_cur[idx + 2] = excl + c0 + c1; }
    if (idx + 3 < NN) { g_start[idx + 3] = excl + c0 + c1 + c2; g_cur[idx + 3] = excl + c0 + c1 + c2; }
}

__global__ void __launch_bounds__(256)
k_scatter(const int* __restrict__ adj, const float* __restrict__ vals) {
    size_t e = (size_t)blockIdx.x * 256 + threadIdx.x;
    if (e >= (size_t)NE) return;
    int r, c;
    if (g_is64) {
        const long long* a64 = (const long long*)adj;
        r = (int)__ldcs(a64 + e);
        c = (int)__ldcs(a64 + (size_t)NE + e);
    } else {
        r = __ldcs(adj + e);
        c = __ldcs(adj + (size_t)NE + e);
    }
    float v = __ldcs(vals + e);
    int pos = atomicAdd(&g_cur[r], 1);
    __stcs(&g_csr[pos], make_int2(c, __float_as_int(v)));
}

// ---------------- per-layer kernels ----------------

__global__ void __launch_bounds__(512)
k_zeroG() {
    int t = threadIdx.x;
    float* g = &g_G[0][0];
    for (int i = t; i < 2 * DD * DD; i += blockDim.x) g[i] = 0.0f;
}

// G[part] = E0_part^T @ prev_part   (32x32 each)
__global__ void __launch_bounds__(256, 2)
k_G(const float* __restrict__ ue, const float* __restrict__ ie, int dir) {
    const float* prev = dir ? g_bufB : g_bufA;
    int b = blockIdx.x;
    const float* e0; const float* pv; float* Gout; int r0, r1;
    if (b < GB_USER) {
        e0 = ue; pv = prev; Gout = g_G[0];
        const int per = (NU + GB_USER - 1) / GB_USER;
        r0 = b * per; r1 = min(r0 + per, NU);
    } else {
        int bb = b - GB_USER;
        e0 = ie; pv = prev + (size_t)NU * DD; Gout = g_G[1];
        const int per = (NI + GB_ITEM - 1) / GB_ITEM;
        r0 = bb * per; r1 = min(r0 + per, NI);
    }
    int t = threadIdx.x;
    int q  = t >> 6;          // row subgroup 0..3
    int g  = t & 63;          // cell-thread 0..63
    int a4 = g >> 3;          // rows a4*4..+3 of G
    int b4 = g & 7;           // cols b4*4..+3 of G

    float4 acc0 = {0,0,0,0}, acc1 = {0,0,0,0}, acc2 = {0,0,0,0}, acc3 = {0,0,0,0};

    #pragma unroll 2
    for (int r = r0 + q; r < r1; r += 4) {
        float4 e4 = *(const float4*)(e0 + (size_t)r * DD + a4 * 4);
        float4 p4 = *(const float4*)(pv + (size_t)r * DD + b4 * 4);
        acc0 = f4_fma(e4.x, p4, acc0);
        acc1 = f4_fma(e4.y, p4, acc1);
        acc2 = f4_fma(e4.z, p4, acc2);
        acc3 = f4_fma(e4.w, p4, acc3);
    }

    __shared__ float red[4 * 1024];
    float* my = red + q * 1024 + g * 16;
    ((float4*)my)[0] = acc0;
    ((float4*)my)[1] = acc1;
    ((float4*)my)[2] = acc2;
    ((float4*)my)[3] = acc3;
    __syncthreads();

    for (int idx = t; idx < 1024; idx += 256) {
        int gg = idx >> 4, i = idx & 15;
        float s = red[0 * 1024 + gg * 16 + i] + red[1 * 1024 + gg * 16 + i]
                + red[2 * 1024 + gg * 16 + i] + red[3 * 1024 + gg * 16 + i];
        int a  = (gg >> 3) * 4 + (i >> 2);
        int bc = (gg & 7) * 4 + (i & 3);
        atomicAdd(&Gout[a * DD + bc], s);
    }
}

// M[part] = W (W^T G[part]);  W is [32,128] row-major. grid = 2 blocks, 256 thr.
__global__ void __launch_bounds__(256, 1)
k_M(const float* __restrict__ uW, const float* __restrict__ iW) {
    int part = blockIdx.x;
    const float* W = part ? iW : uW;
    __shared__ float Wsh[32 * NH];
    __shared__ float Tsh[NH * 32];
    __shared__ float Gsh[32 * 32];
    int t = threadIdx.x;
    for (int i = t; i < 32 * NH; i += 256) Wsh[i] = W[i];
    for (int i = t; i < 1024; i += 256) Gsh[i] = g_G[part][i];
    __syncthreads();
    for (int idx = t; idx < NH * 32; idx += 256) {
        int h = idx >> 5, bcol = idx & 31;
        float s = 0.0f;
        #pragma unroll 8
        for (int a = 0; a < 32; a++) s = fmaf(Wsh[a * NH + h], Gsh[a * 32 + bcol], s);
        Tsh[h * 32 + bcol] = s;
    }
    __syncthreads();
    for (int idx = t; idx < 1024; idx += 256) {
        int a = idx >> 5, bcol = idx & 31;
        float s = 0.0f;
        #pragma unroll 8
        for (int h = 0; h < NH; h++) s = fmaf(Wsh[a * NH + h], Tsh[h * 32 + bcol], s);
        g_M[part][idx] = s;
    }
}

// Fused per-layer: next[r] = gcn(prev)[r] + lrelu(E0[r] @ M[part]); out[r] += next[r].
// Warp = 4 rows x 8 threads; thread owns a 16B column chunk (c4). CSR gather:
// one LDG.128 warp-instruction covers 4 edges' src data. No atomics.
__global__ void __launch_bounds__(256)
k_fused(const float* __restrict__ ue, const float* __restrict__ ie,
        float* __restrict__ out, int dir) {
    const float* src = dir ? g_bufB : g_bufA;
    float*       nxt = dir ? g_bufA : g_bufB;

    __shared__ float Msh[2 * 1024];
    int t = threadIdx.x;
    #pragma unroll
    for (int i = 0; i < 8; i++) Msh[i * 256 + t] = ((const float*)g_M)[i * 256 + t];
    __syncthreads();

    int w = t >> 5, lane = t & 31;
    int rr = lane >> 3;           // row within warp quad
    int c4 = lane & 7;            // 16B chunk index
    int r = (blockIdx.x * 8 + w) * 4 + rr;      // NN % 32 == 0, exact

    const float* e0; const float* Mp;
    if (r < NU) { e0 = ue + (size_t)r * DD;        Mp = Msh; }
    else        { e0 = ie + (size_t)(r - NU) * DD; Mp = Msh + 1024; }

    // hyp: acc[j] = sum_k e0[k] * M[k][c4*4+j], via width-8 shfl broadcast
    float4 e4 = *(const float4*)(e0 + c4 * 4);
    float4 acc = {0, 0, 0, 0};
    int gbase = lane & 24;        // 8-thread group base lane
    #pragma unroll
    for (int k = 0; k < 32; k++) {
        float comp = (k & 3) == 0 ? e4.x : (k & 3) == 1 ? e4.y
                   : (k & 3) == 2 ? e4.z : e4.w;
        float ek = __shfl_sync(0xffffffffu, comp, gbase | (k >> 2));
        float4 m4 = *(const float4*)(Mp + k * 32 + c4 * 4);
        acc = f4_fma(ek, m4, acc);
    }
    acc.x = lrelu(acc.x); acc.y = lrelu(acc.y);
    acc.z = lrelu(acc.z); acc.w = lrelu(acc.w);

    // gcn: per-row CSR gather; 4-deep unroll for MLP
    int start = g_start[r];
    int end   = start + g_cnt[r];
    int i = start;
    for (; i + 4 <= end; i += 4) {
        int2 cv0 = __ldcs(&g_csr[i]);
        int2 cv1 = __ldcs(&g_csr[i + 1]);
        int2 cv2 = __ldcs(&g_csr[i + 2]);
        int2 cv3 = __ldcs(&g_csr[i + 3]);
        float4 s0 = *(const float4*)(src + (size_t)cv0.x * DD + c4 * 4);
        float4 s1 = *(const float4*)(src + (size_t)cv1.x * DD + c4 * 4);
        float4 s2 = *(const float4*)(src + (size_t)cv2.x * DD + c4 * 4);
        float4 s3 = *(const float4*)(src + (size_t)cv3.x * DD + c4 * 4);
        acc = f4_fma(__int_as_float(cv0.y), s0, acc);
        acc = f4_fma(__int_as_float(cv1.y), s1, acc);
        acc = f4_fma(__int_as_float(cv2.y), s2, acc);
        acc = f4_fma(__int_as_float(cv3.y), s3, acc);
    }
    for (; i < end; i++) {
        int2 cv = __ldcs(&g_csr[i]);
        float4 s = *(const float4*)(src + (size_t)cv.x * DD + c4 * 4);
        acc = f4_fma(__int_as_float(cv.y), s, acc);
    }

    size_t o = (size_t)r * DD + c4 * 4;
    *(float4*)(nxt + o) = acc;
    float4 ov = *(float4*)(out + o);
    ov.x += acc.x; ov.y += acc.y; ov.z += acc.z; ov.w += acc.w;
    *(float4*)(out + o) = ov;
}

// ---------------- launch ----------------
extern "C" void kernel_launch(void* const* d_in, const int* in_sizes, int n_in,
                              void* d_out, int out_size) {
    // Identify inputs by element count (robust to harness ordering)
    const int* adj = nullptr; const float* vals = nullptr;
    const float* ue = nullptr; const float* ie = nullptr;
    const float* h1 = nullptr; const float* h2 = nullptr;
    int i_ue = -1, i_ie = -1;
    for (int i = 0; i < n_in; i++) {
        long long s = in_sizes[i];
        if (s == 2LL * NE)              adj = (const int*)d_in[i];
        else if (s == (long long)NE)    vals = (const float*)d_in[i];
        else if (s == (long long)NU * DD) { ue = (const float*)d_in[i]; i_ue = i; }
        else if (s == (long long)NI * DD) { ie = (const float*)d_in[i]; i_ie = i; }
        else if (s == (long long)DD * NH) { if (!h1) h1 = (const float*)d_in[i]; else h2 = (const float*)d_in[i]; }
    }
    const float* uW; const float* iW;
    if (i_ue < i_ie) { uW = h1; iW = h2; }
    else             { uW = h2; iW = h1; }
    float* out = (float*)d_out;

    const int nb_nd    = (NN * DD / 4 + 255) / 256;           // 18750
    const int nb_edge  = (int)(((size_t)NE + 255) / 256);     // 39063
    const int nb_fused = NN / 32;                             // 18750 (8 warps x 4 rows)
    const int nb_cnt   = (NN + 255) / 256;

    k_dz<<<nb_cnt, 256>>>(adj);
    k_init<<<nb_nd, 256>>>(ue, ie, out);

    // CSR build
    k_hist<<<nb_edge, 256>>>(adj);
    k_scan1<<<NB_SCAN, 1024>>>();
    k_scan2<<<1, 256>>>();
    k_scan3<<<NB_SCAN, 1024>>>();
    k_scatter<<<nb_edge, 256>>>(adj, vals);

    for (int layer = 0; layer < 2; layer++) {
        k_zeroG<<<1, 512>>>();
        k_G<<<GB_USER + GB_ITEM, 256>>>(ue, ie, layer);
        k_M<<<2, 256>>>(uW, iW);
        k_fused<<<nb_fused, 256>>>(ue, ie, out, layer);
    }
}